// round 3
// baseline (speedup 1.0000x reference)
#include <cuda_runtime.h>
#include <math.h>

// Problem constants
#define BB 16
#define PP 12
#define QQ 12
#define NN 1024
#define DD 64
#define HH 32
#define ROWCAP 128
#define PANEL (16384*128)   // one Chebyshev term: (B*N) x 128

// ---------------- scratch (device globals; no runtime allocation) ----------
__device__ float g_se[NN*HH];                // (N,32)
__device__ float g_te[BB*24*HH];             // (B,24,32)
__device__ float g_x[BB*PP*NN*DD];           // (B,P,N,64)  input embedding
__device__ float g_cheb[4*PANEL];            // 4 terms x (16384 x 128)
__device__ float g_ru[16384*128];            // sigmoid gates
__device__ float g_h[16384*64];              // hidden state
__device__ int   g_col[NN*ROWCAP];
__device__ float g_val[NN*ROWCAP];
__device__ int   g_nnz[NN];

// ---------------- small embeddings: se (N,32) and te (B,24,32) -------------
__global__ void k_small(const float* __restrict__ SE,
                        const float* __restrict__ Wse1, const float* __restrict__ bse1,
                        const float* __restrict__ Wse2, const float* __restrict__ bse2,
                        const float* __restrict__ Wte1, const float* __restrict__ bte1,
                        const float* __restrict__ Wte2, const float* __restrict__ bte2,
                        const int* __restrict__ TE){
  int tid = threadIdx.x;
  if (blockIdx.x < 4){
    int n = blockIdx.x*256 + tid;
    float in[32], hid[32];
    #pragma unroll
    for (int k=0;k<32;k++) in[k] = SE[n*32+k];
    #pragma unroll
    for (int j=0;j<32;j++){
      float a = bse1[j];
      #pragma unroll
      for (int k=0;k<32;k++) a = fmaf(in[k], Wse1[k*32+j], a);
      hid[j] = fmaxf(a, 0.f);
    }
    #pragma unroll
    for (int j=0;j<32;j++){
      float a = bse2[j];
      #pragma unroll
      for (int k=0;k<32;k++) a = fmaf(hid[k], Wse2[k*32+j], a);
      g_se[n*32+j] = a;
    }
  } else {
    int i = (blockIdx.x-4)*256 + tid;      // (b,t) flat, t in [0,24)
    if (i < BB*24){
      int day = TE[i*2+0], tod = TE[i*2+1];
      float hid[32];
      #pragma unroll
      for (int j=0;j<32;j++)
        hid[j] = fmaxf(Wte1[day*32+j] + Wte1[(7+tod)*32+j] + bte1[j], 0.f);
      #pragma unroll
      for (int j=0;j<32;j++){
        float a = bte2[j];
        #pragma unroll
        for (int k=0;k<32;k++) a = fmaf(hid[k], Wte2[k*32+j], a);
        g_te[i*32+j] = a;
      }
    }
  }
}

// ---------------- CSR extraction of L_s (deterministic, ascending cols) ----
__global__ void k_csr(const float* __restrict__ Ls){
  int w = (blockIdx.x*blockDim.x + threadIdx.x) >> 5;
  int lane = threadIdx.x & 31;
  if (w >= NN) return;
  const float* row = Ls + (size_t)w*NN;
  int cnt = 0;
  for (int c0=0;c0<NN;c0+=32){
    float v = row[c0+lane];
    unsigned msk = __ballot_sync(0xffffffffu, v != 0.f);
    if (v != 0.f){
      int pos = cnt + __popc(msk & ((1u<<lane)-1u));
      if (pos < ROWCAP){ g_col[w*ROWCAP+pos]=c0+lane; g_val[w*ROWCAP+pos]=v; }
    }
    cnt += __popc(msk);
  }
  if (lane==0) g_nnz[w] = cnt < ROWCAP ? cnt : ROWCAP;
}

// ---------------- input embedding + ZC conv + STE add, writes g_x ----------
__global__ void __launch_bounds__(256) k_embed(const float* __restrict__ X,
                        const float* __restrict__ ZC,
                        const float* __restrict__ Wconv, const float* __restrict__ bconv,
                        const float* __restrict__ W1, const float* __restrict__ b1,
                        const float* __restrict__ W2, const float* __restrict__ b2){
  __shared__ float sWc[98*32];
  __shared__ float sW2[64*32];
  __shared__ float sW1[64], sb1[64], sb2[32], sbc[32];
  __shared__ float srow[8][100];
  __shared__ float shid[8][64];
  int tid = threadIdx.x;
  for (int i=tid;i<98*32;i+=256) sWc[i]=Wconv[i];
  for (int i=tid;i<64*32;i+=256) sW2[i]=W2[i];
  if (tid<64){ sW1[tid]=W1[tid]; sb1[tid]=b1[tid]; }
  if (tid<32){ sb2[tid]=b2[tid]; sbc[tid]=bconv[tid]; }
  __syncthreads();
  int warp = tid>>5, lane = tid&31;
  int row = blockIdx.x*8 + warp;                 // < 196608 exactly
  const float* z = ZC + (size_t)row*98;
  for (int i=lane;i<98;i+=32) srow[warp][i]=z[i];
  float xval = X[row];
  shid[warp][lane]      = fmaxf(fmaf(xval, sW1[lane],    sb1[lane]),    0.f);
  shid[warp][lane+32]   = fmaxf(fmaf(xval, sW1[lane+32], sb1[lane+32]), 0.f);
  __syncwarp();
  float zacc = sbc[lane];
  #pragma unroll
  for (int i=0;i<98;i++) zacc = fmaf(srow[warp][i], sWc[i*32+lane], zacc);
  zacc = fmaxf(zacc, 0.f);
  float e = sb2[lane];
  #pragma unroll
  for (int k=0;k<64;k++) e = fmaf(shid[warp][k], sW2[k*32+lane], e);
  int b = row/(PP*NN); int pn = row%(PP*NN); int p = pn/NN; int n = pn%NN;
  float ste = g_se[n*32+lane] + g_te[(b*24+p)*32+lane];
  g_x[(size_t)row*64 + lane]      = e + ste;
  g_x[(size_t)row*64 + 32 + lane] = zacc;
}

// ---------------- zero hidden state ----------------------------------------
__global__ void k_zeroh(){
  for (int i = blockIdx.x*blockDim.x + threadIdx.x; i < 16384*64;
       i += gridDim.x*blockDim.x)
    g_h[i] = 0.f;
}

// ---------------- concat kernels: build Chebyshev term 0 -------------------
__global__ void k_concat_g(int t){
  int i = blockIdx.x*blockDim.x + threadIdx.x;   // < 2,097,152
  int row = i>>7, c = i&127;
  int b = row>>10, n = row&1023;
  float v;
  if (c < 64) v = g_x[((size_t)((b*12 + t)*1024 + n))*64 + c];
  else        v = g_h[(size_t)row*64 + (c-64)];
  g_cheb[i] = v;
}
__global__ void k_concat_c(int t){
  int i = blockIdx.x*blockDim.x + threadIdx.x;
  int row = i>>7, c = i&127;
  int b = row>>10, n = row&1023;
  float v;
  if (c < 64) v = g_x[((size_t)((b*12 + t)*1024 + n))*64 + c];
  else        v = g_ru[(size_t)row*128 + (c-64)] * g_h[(size_t)row*64 + (c-64)];
  g_cheb[i] = v;
}

// ---------------- SpMM: out = scale * (L_s @ xin) + adds * xadd ------------
// Stages x[b, :, cc0:cc0+8] in smem; grid = 16 b * 16 chunks = 256 blocks.
__global__ void __launch_bounds__(256) k_spmm(int psrc, int padd, int pdst,
                                              float scale, float adds){
  __shared__ float sx[1024*9];
  const float* xin  = g_cheb + (size_t)psrc*PANEL;
  const float* xadd = g_cheb + (size_t)padd*PANEL;
  float* out        = g_cheb + (size_t)pdst*PANEL;
  int b   = blockIdx.x >> 4;
  int cc0 = (blockIdx.x & 15) * 8;
  const float* xb = xin + ((size_t)b<<10)*128;
  int tid = threadIdx.x;
  #pragma unroll
  for (int it=0; it<8; it++){
    int i = tid + it*256;                  // 0..2047 float4s
    int n = i>>1, q = i&1;
    float4 v = *(const float4*)(xb + n*128 + cc0 + q*4);
    float* d = &sx[n*9 + q*4];
    d[0]=v.x; d[1]=v.y; d[2]=v.z; d[3]=v.w;
  }
  __syncthreads();
  int cc = tid & 7;
  int msub = tid >> 3;                      // 0..31
  for (int m = msub; m < 1024; m += 32){
    int nnz = g_nnz[m];
    const int*   cols = g_col + m*ROWCAP;
    const float* vals = g_val + m*ROWCAP;
    float acc0=0.f, acc1=0.f;
    int j=0;
    for (; j+1<nnz; j+=2){
      acc0 = fmaf(vals[j],   sx[cols[j]*9   + cc], acc0);
      acc1 = fmaf(vals[j+1], sx[cols[j+1]*9 + cc], acc1);
    }
    if (j<nnz) acc0 = fmaf(vals[j], sx[cols[j]*9 + cc], acc0);
    size_t o = ((size_t)((b<<10) | m))*128 + cc0 + cc;
    out[o] = scale*(acc0+acc1) + adds*xadd[o];
  }
}

// ---------------- tiled SGEMM, plain FFMA register tiles -------------------
// C = [cheb0|cheb1|cheb2|cheb3] (M=16384, K=512) @ W (512 x BN), epilogue:
//   EPI==0: ru = sigmoid(. + bias)                (BN=128)
//   EPI==1: c  = tanh(. + bias); h = u*h+(1-u)*c  (BN=64)
template<int BN, int EPI>
__global__ void __launch_bounds__(16*(BN/8)) k_gemm(const float* __restrict__ W,
                                                    const float* __restrict__ bias){
  constexpr int NT = 16*(BN/8);
  __shared__ float As[16][132];
  __shared__ float Bs[16][BN];
  int tid = threadIdx.x;
  int m0 = blockIdx.x*128;
  int ty = tid/(BN/8), tx = tid%(BN/8);
  float acc[8][8];
  #pragma unroll
  for (int i=0;i<8;i++)
    #pragma unroll
    for (int j=0;j<8;j++) acc[i][j] = 0.f;

  #pragma unroll
  for (int k4=0;k4<4;k4++){
    const float* Ap = g_cheb + (size_t)k4*PANEL + (size_t)m0*128;
    const float* Wp = W + (size_t)(k4*128)*BN;
    for (int kk=0; kk<128; kk+=16){
      __syncthreads();
      #pragma unroll
      for (int it=0; it<512/NT; it++){
        int i = tid + it*NT;               // 0..511 float4s of A tile
        int m = i>>2, q = i&3;
        float4 v = *(const float4*)(Ap + m*128 + kk + q*4);
        As[q*4+0][m]=v.x; As[q*4+1][m]=v.y; As[q*4+2][m]=v.z; As[q*4+3][m]=v.w;
      }
      #pragma unroll
      for (int it=0; it<(16*BN/4)/NT; it++){
        int i = tid + it*NT;
        int k = i/(BN/4), n4 = i%(BN/4);
        *(float4*)&Bs[k][n4*4] = *(const float4*)(Wp + (size_t)(kk+k)*BN + n4*4);
      }
      __syncthreads();
      #pragma unroll
      for (int k=0;k<16;k++){
        float a[8], bv[8];
        #pragma unroll
        for (int i=0;i<8;i++) a[i]=As[k][ty*8+i];
        #pragma unroll
        for (int j=0;j<8;j++) bv[j]=Bs[k][tx*8+j];
        #pragma unroll
        for (int i=0;i<8;i++)
          #pragma unroll
          for (int j=0;j<8;j++) acc[i][j] = fmaf(a[i], bv[j], acc[i][j]);
      }
    }
  }
  #pragma unroll
  for (int i=0;i<8;i++){
    size_t row = m0 + ty*8 + i;
    #pragma unroll
    for (int j=0;j<8;j++){
      int c0 = tx*8 + j;
      float v = acc[i][j] + bias[c0];
      if (EPI==0){
        g_ru[row*128 + c0] = 1.f/(1.f+expf(-v));
      } else {
        float cand = tanhf(v);
        float u = g_ru[row*128 + 64 + c0];
        float h = g_h[row*64 + c0];
        g_h[row*64 + c0] = u*h + (1.f-u)*cand;
      }
    }
  }
}

// ---------------- output head ----------------------------------------------
__global__ void __launch_bounds__(256) k_out(const float* __restrict__ Wo1,
                        const float* __restrict__ bo1,
                        const float* __restrict__ Wo2, const float* __restrict__ bo2,
                        float* __restrict__ out){
  __shared__ float sW1[64*64];
  __shared__ float sW2[64*12];
  __shared__ float sb1[64], sb2[12];
  __shared__ float shrow[8][64];
  __shared__ float shid[8][64];
  int tid = threadIdx.x;
  for (int i=tid;i<64*64;i+=256) sW1[i]=Wo1[i];
  for (int i=tid;i<64*12;i+=256) sW2[i]=Wo2[i];
  if (tid<64) sb1[tid]=bo1[tid];
  if (tid<12) sb2[tid]=bo2[tid];
  __syncthreads();
  int warp = tid>>5, lane = tid&31;
  int row = blockIdx.x*8 + warp;            // < 16384 exactly
  shrow[warp][lane]    = g_h[(size_t)row*64 + lane];
  shrow[warp][lane+32] = g_h[(size_t)row*64 + lane + 32];
  __syncwarp();
  #pragma unroll
  for (int half=0; half<2; half++){
    int jj = lane + half*32;
    float a = sb1[jj];
    #pragma unroll
    for (int k=0;k<64;k++) a = fmaf(shrow[warp][k], sW1[k*64+jj], a);
    shid[warp][jj] = fmaxf(a, 0.f);
  }
  __syncwarp();
  if (lane < 12){
    float a = sb2[lane];
    #pragma unroll
    for (int k=0;k<64;k++) a = fmaf(shid[warp][k], sW2[k*12+lane], a);
    int b = row>>10, n = row&1023;
    out[(size_t)(b*12 + lane)*1024 + n] = a;
  }
}

// ---------------- host launcher --------------------------------------------
extern "C" void kernel_launch(void* const* d_in, const int* in_sizes, int n_in,
                              void* d_out, int out_size){
  const float* X     = (const float*)d_in[0];
  const float* ZC    = (const float*)d_in[1];
  const int*   TE    = (const int*)  d_in[2];
  const float* Ls    = (const float*)d_in[3];
  const float* SE    = (const float*)d_in[4];
  const float* Wse1  = (const float*)d_in[5];
  const float* bse1  = (const float*)d_in[6];
  const float* Wse2  = (const float*)d_in[7];
  const float* bse2  = (const float*)d_in[8];
  const float* Wte1  = (const float*)d_in[9];
  const float* bte1  = (const float*)d_in[10];
  const float* Wte2  = (const float*)d_in[11];
  const float* bte2  = (const float*)d_in[12];
  const float* Win1  = (const float*)d_in[13];
  const float* bin1  = (const float*)d_in[14];
  const float* Win2  = (const float*)d_in[15];
  const float* bin2  = (const float*)d_in[16];
  const float* Wconv = (const float*)d_in[17];
  const float* bconv = (const float*)d_in[18];
  const float* Wg    = (const float*)d_in[19];
  const float* bg    = (const float*)d_in[20];
  const float* Wc    = (const float*)d_in[21];
  const float* bc    = (const float*)d_in[22];
  const float* Wo1   = (const float*)d_in[23];
  const float* bo1   = (const float*)d_in[24];
  const float* Wo2   = (const float*)d_in[25];
  const float* bo2   = (const float*)d_in[26];
  float* out = (float*)d_out;

  k_zeroh<<<512,256>>>();
  k_small<<<6,256>>>(SE,Wse1,bse1,Wse2,bse2,Wte1,bte1,Wte2,bte2,TE);
  k_csr<<<32,1024>>>(Ls);
  k_embed<<<24576,256>>>(X,ZC,Wconv,bconv,Win1,bin1,Win2,bin2);

  for (int t=0;t<12;t++){
    k_concat_g<<<8192,256>>>(t);
    k_spmm<<<256,256>>>(0,0,1, 1.f,  0.f);
    k_spmm<<<256,256>>>(1,0,2, 2.f, -1.f);
    k_spmm<<<256,256>>>(2,1,3, 2.f, -1.f);
    k_gemm<128,0><<<128,256>>>(Wg,bg);
    k_concat_c<<<8192,256>>>(t);
    k_spmm<<<256,256>>>(0,0,1, 1.f,  0.f);
    k_spmm<<<256,256>>>(1,0,2, 2.f, -1.f);
    k_spmm<<<256,256>>>(2,1,3, 2.f, -1.f);
    k_gemm<64,1><<<128,128>>>(Wc,bc);
  }
  k_out<<<2048,256>>>(Wo1,bo1,Wo2,bo2,out);
}

// round 5
// speedup vs baseline: 1.3236x; 1.3236x over previous
#include <cuda_runtime.h>
#include <math.h>

// Problem constants
#define BB 16
#define PP 12
#define QQ 12
#define NN 1024
#define DD 64
#define HH 32
#define ROWCAP 128
#define MPRE (BB*PP*NN)      // 196608 rows for precompute
#define MSTEP (BB*NN)        // 16384 rows per step

// ---------------- scratch (device globals; no runtime allocation) ----------
__device__ float g_se[NN*HH];
__device__ float g_te[BB*24*HH];
__device__ float g_x [MPRE*64];      // input embedding (b,t,n,64)   id 0
__device__ float g_px1[MPRE*64];     // x Chebyshev terms            id 1
__device__ float g_px2[MPRE*64];     //                              id 2
__device__ float g_px3[MPRE*64];     //                              id 3
__device__ float g_Gx[(size_t)MPRE*128]; // precomputed x-part of gates
__device__ float g_Cx[MPRE*64];          // precomputed x-part of candidate
__device__ float g_h  [MSTEP*64];    // hidden state                 id 4
__device__ float g_ph1[MSTEP*64];    // per-step diffusion panels    id 5
__device__ float g_ph2[MSTEP*64];    //                              id 6
__device__ float g_ph3[MSTEP*64];    //                              id 7
__device__ float g_prh[MSTEP*64];    // r*h                          id 8
__device__ float g_u  [MSTEP*64];    // update gate
__device__ int2  g_ev [NN*ROWCAP];   // packed CSR: {col*9, float_bits(val)}
__device__ int   g_nnz[NN];

__device__ __forceinline__ float* panel(int id){
  switch(id){
    case 0: return g_x;   case 1: return g_px1;
    case 2: return g_px2; case 3: return g_px3;
    case 4: return g_h;   case 5: return g_ph1;
    case 6: return g_ph2; case 7: return g_ph3;
    default: return g_prh;
  }
}

// ---------------- small embeddings: se (N,32) and te (B,24,32) -------------
__global__ void k_small(const float* __restrict__ SE,
                        const float* __restrict__ Wse1, const float* __restrict__ bse1,
                        const float* __restrict__ Wse2, const float* __restrict__ bse2,
                        const float* __restrict__ Wte1, const float* __restrict__ bte1,
                        const float* __restrict__ Wte2, const float* __restrict__ bte2,
                        const int* __restrict__ TE){
  int tid = threadIdx.x;
  if (blockIdx.x < 4){
    int n = blockIdx.x*256 + tid;
    float in[32], hid[32];
    #pragma unroll
    for (int k=0;k<32;k++) in[k] = SE[n*32+k];
    #pragma unroll
    for (int j=0;j<32;j++){
      float a = bse1[j];
      #pragma unroll
      for (int k=0;k<32;k++) a = fmaf(in[k], Wse1[k*32+j], a);
      hid[j] = fmaxf(a, 0.f);
    }
    #pragma unroll
    for (int j=0;j<32;j++){
      float a = bse2[j];
      #pragma unroll
      for (int k=0;k<32;k++) a = fmaf(hid[k], Wse2[k*32+j], a);
      g_se[n*32+j] = a;
    }
  } else {
    int i = (blockIdx.x-4)*256 + tid;      // (b,t) flat, t in [0,24)
    if (i < BB*24){
      int day = TE[i*2+0], tod = TE[i*2+1];
      float hid[32];
      #pragma unroll
      for (int j=0;j<32;j++)
        hid[j] = fmaxf(Wte1[day*32+j] + Wte1[(7+tod)*32+j] + bte1[j], 0.f);
      #pragma unroll
      for (int j=0;j<32;j++){
        float a = bte2[j];
        #pragma unroll
        for (int k=0;k<32;k++) a = fmaf(hid[k], Wte2[k*32+j], a);
        g_te[i*32+j] = a;
      }
    }
  }
}

// ---------------- CSR extraction of L_s (packed int2, cols ascending) ------
__global__ void k_csr(const float* __restrict__ Ls){
  int w = (blockIdx.x*blockDim.x + threadIdx.x) >> 5;
  int lane = threadIdx.x & 31;
  if (w >= NN) return;
  const float* row = Ls + (size_t)w*NN;
  int cnt = 0;
  for (int c0=0;c0<NN;c0+=32){
    float v = row[c0+lane];
    unsigned msk = __ballot_sync(0xffffffffu, v != 0.f);
    if (v != 0.f){
      int pos = cnt + __popc(msk & ((1u<<lane)-1u));
      if (pos < ROWCAP) g_ev[w*ROWCAP+pos] = make_int2((c0+lane)*9, __float_as_int(v));
    }
    cnt += __popc(msk);
  }
  if (lane==0) g_nnz[w] = cnt < ROWCAP ? cnt : ROWCAP;
}

// ---------------- input embedding + ZC conv + STE add, writes g_x ----------
// 8 warps/block, 4 rows/warp (4 independent FMA chains per lane).
__global__ void __launch_bounds__(256) k_embed(const float* __restrict__ X,
                        const float* __restrict__ ZC,
                        const float* __restrict__ Wconv, const float* __restrict__ bconv,
                        const float* __restrict__ W1, const float* __restrict__ b1,
                        const float* __restrict__ W2, const float* __restrict__ b2){
  __shared__ float sWc[98*32];
  __shared__ float sW2[64*32];
  __shared__ float sW1[64], sb1[64], sb2[32], sbc[32];
  __shared__ float srow[8][4][100];
  __shared__ float shid[8][4][64];
  int tid = threadIdx.x;
  for (int i=tid;i<98*32;i+=256) sWc[i]=Wconv[i];
  for (int i=tid;i<64*32;i+=256) sW2[i]=W2[i];
  if (tid<64){ sW1[tid]=W1[tid]; sb1[tid]=b1[tid]; }
  if (tid<32){ sb2[tid]=b2[tid]; sbc[tid]=bconv[tid]; }
  __syncthreads();
  int warp = tid>>5, lane = tid&31;
  int r0 = (blockIdx.x*8 + warp)*4;
  #pragma unroll
  for (int rr=0; rr<4; rr++){
    int row = r0 + rr;
    const float2* z = (const float2*)(ZC + (size_t)row*98);
    for (int i=lane;i<49;i+=32) *(float2*)&srow[warp][rr][2*i] = z[i];
    float xv = X[row];
    shid[warp][rr][lane]    = fmaxf(fmaf(xv, sW1[lane],    sb1[lane]),    0.f);
    shid[warp][rr][lane+32] = fmaxf(fmaf(xv, sW1[lane+32], sb1[lane+32]), 0.f);
  }
  __syncwarp();
  float zacc[4], e[4];
  #pragma unroll
  for (int rr=0;rr<4;rr++){ zacc[rr]=sbc[lane]; e[rr]=sb2[lane]; }
  #pragma unroll 2
  for (int i=0;i<98;i++){
    float w = sWc[i*32+lane];
    #pragma unroll
    for (int rr=0;rr<4;rr++) zacc[rr] = fmaf(srow[warp][rr][i], w, zacc[rr]);
  }
  #pragma unroll 2
  for (int k=0;k<64;k++){
    float w2 = sW2[k*32+lane];
    #pragma unroll
    for (int rr=0;rr<4;rr++) e[rr] = fmaf(shid[warp][rr][k], w2, e[rr]);
  }
  #pragma unroll
  for (int rr=0;rr<4;rr++){
    int row = r0 + rr;
    int b = row/(PP*NN); int pn = row%(PP*NN); int p = pn>>10; int n = pn&1023;
    float ste = g_se[n*32+lane] + g_te[(b*24+p)*32+lane];
    g_x[(size_t)row*64 + lane]      = e[rr] + ste;
    g_x[(size_t)row*64 + 32 + lane] = fmaxf(zacc[rr], 0.f);
  }
}

// ---------------- zero hidden state ----------------------------------------
__global__ void k_zeroh(){
  for (int i = blockIdx.x*blockDim.x + threadIdx.x; i < MSTEP*64;
       i += gridDim.x*blockDim.x)
    g_h[i] = 0.f;
}

// ---------------- SpMM: dst = scale * (L_s @ src) + adds * xadd ------------
// panels: (G*1024) x 64. Block = (group, 8-col chunk). 512 threads.
__global__ void __launch_bounds__(512) k_spmm(int sid, int aid, int did,
                                              float scale, float adds){
  __shared__ float sx[1024*9];
  const float* src  = panel(sid);
  const float* xadd = panel(aid);
  float* dst        = panel(did);
  int g  = blockIdx.x >> 3;
  int c0 = (blockIdx.x & 7) * 8;
  const float* sp = src + (size_t)g*1024*64;
  int tid = threadIdx.x;
  for (int i=tid; i<2048; i+=512){
    int n = i>>1, q = i&1;
    float4 v = *(const float4*)(sp + n*64 + c0 + q*4);
    float* d = &sx[n*9 + q*4];
    d[0]=v.x; d[1]=v.y; d[2]=v.z; d[3]=v.w;
  }
  __syncthreads();
  int cc = tid & 7;
  int m0 = tid >> 3;                 // 0..63
  for (int m=m0; m<1024; m+=64){
    int nnz = g_nnz[m];
    const int2* ev = g_ev + m*ROWCAP;
    float a0=0.f,a1=0.f,a2=0.f,a3=0.f;
    int j=0;
    for (; j+4<=nnz; j+=4){
      int4 e0 = *(const int4*)(ev+j);
      int4 e1 = *(const int4*)(ev+j+2);
      a0 = fmaf(__int_as_float(e0.y), sx[e0.x+cc], a0);
      a1 = fmaf(__int_as_float(e0.w), sx[e0.z+cc], a1);
      a2 = fmaf(__int_as_float(e1.y), sx[e1.x+cc], a2);
      a3 = fmaf(__int_as_float(e1.w), sx[e1.z+cc], a3);
    }
    for (; j<nnz; j++){
      int2 e = ev[j];
      a0 = fmaf(__int_as_float(e.y), sx[e.x+cc], a0);
    }
    size_t o = ((size_t)g*1024 + m)*64 + c0 + cc;
    dst[o] = scale*((a0+a1)+(a2+a3)) + adds*xadd[o];
  }
}

// ---------------- FFMA GEMM: D = [A0|A1|A2|A3](Mx256) @ W(256xBN) ----------
// W row for (term k, local feature f) = k*128 + woff + f.
// EPI 2 (BN=192): raw store, cols 0..127 -> Gx, 128..191 -> Cx  (M=196608)
// EPI 0 (BN=128): sigmoid(D+Gx+bias); col<64 -> prh=r*h, col>=64 -> u
// EPI 1 (BN=64):  c=tanh(D+Cx+bias);  h = u*h+(1-u)*c
template<int BN, int EPI>
__global__ void __launch_bounds__(2*BN) k_gemm(int p0, int p1, int p2, int p3,
                        const float* __restrict__ W1, const float* __restrict__ W2,
                        int woff, const float* __restrict__ bias, int t){
  constexpr int NT = 2*BN;
  constexpr int LDW1 = (BN==64) ? 64 : 128;
  __shared__ float As[16][132];
  __shared__ float Bs[16][BN];
  int tid = threadIdx.x;
  int m0 = blockIdx.x*128;
  int ty = tid/(BN/8), tx = tid%(BN/8);
  float acc[8][8];
  #pragma unroll
  for (int i=0;i<8;i++)
    #pragma unroll
    for (int j=0;j<8;j++) acc[i][j] = 0.f;

  #pragma unroll
  for (int kt=0; kt<4; kt++){
    const float* Ap = panel(kt==0 ? p0 : (kt==1 ? p1 : (kt==2 ? p2 : p3)))
                      + (size_t)m0*64;
    for (int kk=0; kk<64; kk+=16){
      __syncthreads();
      for (int i=tid; i<512; i+=NT){
        int m = i>>2, q = i&3;
        float4 v = *(const float4*)(Ap + (size_t)m*64 + kk + q*4);
        As[q*4+0][m]=v.x; As[q*4+1][m]=v.y; As[q*4+2][m]=v.z; As[q*4+3][m]=v.w;
      }
      for (int i=tid; i<16*BN; i+=NT){
        int kr = i/BN, j = i%BN;
        int wrow = kt*128 + woff + kk + kr;
        Bs[kr][j] = (j < LDW1) ? W1[(size_t)wrow*LDW1 + j]
                               : W2[(size_t)wrow*64 + (j-LDW1)];
      }
      __syncthreads();
      #pragma unroll
      for (int k=0;k<16;k++){
        float a[8], bv[8];
        #pragma unroll
        for (int i=0;i<8;i++) a[i]=As[k][ty*8+i];
        #pragma unroll
        for (int j=0;j<8;j++) bv[j]=Bs[k][tx*8+j];
        #pragma unroll
        for (int i=0;i<8;i++)
          #pragma unroll
          for (int j=0;j<8;j++) acc[i][j] = fmaf(a[i], bv[j], acc[i][j]);
      }
    }
  }
  #pragma unroll
  for (int i=0;i<8;i++){
    size_t row = m0 + ty*8 + i;
    #pragma unroll
    for (int j=0;j<8;j++){
      int col = tx*8 + j;
      float v = acc[i][j];
      if (EPI==2){
        if (col < 128) g_Gx[row*128 + col] = v;
        else           g_Cx[row*64 + (col-128)] = v;
      } else {
        size_t xrow = ((row>>10)*12 + t)*1024 + (row&1023);
        if (EPI==0){
          v += g_Gx[xrow*128 + col] + bias[col];
          float s = 1.f/(1.f+expf(-v));
          if (col < 64) g_prh[row*64 + col] = s * g_h[row*64 + col];
          else          g_u  [row*64 + (col-64)] = s;
        } else {
          v += g_Cx[xrow*64 + col] + bias[col];
          float c = tanhf(v);
          float u = g_u[row*64 + col];
          float h = g_h[row*64 + col];
          g_h[row*64 + col] = u*h + (1.f-u)*c;
        }
      }
    }
  }
}

// ---------------- output head ----------------------------------------------
__global__ void __launch_bounds__(256) k_out(const float* __restrict__ Wo1,
                        const float* __restrict__ bo1,
                        const float* __restrict__ Wo2, const float* __restrict__ bo2,
                        float* __restrict__ out){
  __shared__ float sW1[64*64];
  __shared__ float sW2[64*12];
  __shared__ float sb1[64], sb2[12];
  __shared__ float shrow[8][64];
  __shared__ float shid[8][64];
  int tid = threadIdx.x;
  for (int i=tid;i<64*64;i+=256) sW1[i]=Wo1[i];
  for (int i=tid;i<64*12;i+=256) sW2[i]=Wo2[i];
  if (tid<64) sb1[tid]=bo1[tid];
  if (tid<12) sb2[tid]=bo2[tid];
  __syncthreads();
  int warp = tid>>5, lane = tid&31;
  int row = blockIdx.x*8 + warp;            // < 16384 exactly
  shrow[warp][lane]    = g_h[(size_t)row*64 + lane];
  shrow[warp][lane+32] = g_h[(size_t)row*64 + lane + 32];
  __syncwarp();
  #pragma unroll
  for (int half=0; half<2; half++){
    int jj = lane + half*32;
    float a = sb1[jj];
    #pragma unroll
    for (int k=0;k<64;k++) a = fmaf(shrow[warp][k], sW1[k*64+jj], a);
    shid[warp][jj] = fmaxf(a, 0.f);
  }
  __syncwarp();
  if (lane < 12){
    float a = sb2[lane];
    #pragma unroll
    for (int k=0;k<64;k++) a = fmaf(shid[warp][k], sW2[k*12+lane], a);
    int b = row>>10, n = row&1023;
    out[(size_t)(b*12 + lane)*1024 + n] = a;
  }
}

// ---------------- host launcher --------------------------------------------
extern "C" void kernel_launch(void* const* d_in, const int* in_sizes, int n_in,
                              void* d_out, int out_size){
  const float* X     = (const float*)d_in[0];
  const float* ZC    = (const float*)d_in[1];
  const int*   TE    = (const int*)  d_in[2];
  const float* Ls    = (const float*)d_in[3];
  const float* SE    = (const float*)d_in[4];
  const float* Wse1  = (const float*)d_in[5];
  const float* bse1  = (const float*)d_in[6];
  const float* Wse2  = (const float*)d_in[7];
  const float* bse2  = (const float*)d_in[8];
  const float* Wte1  = (const float*)d_in[9];
  const float* bte1  = (const float*)d_in[10];
  const float* Wte2  = (const float*)d_in[11];
  const float* bte2  = (const float*)d_in[12];
  const float* Win1  = (const float*)d_in[13];
  const float* bin1  = (const float*)d_in[14];
  const float* Win2  = (const float*)d_in[15];
  const float* bin2  = (const float*)d_in[16];
  const float* Wconv = (const float*)d_in[17];
  const float* bconv = (const float*)d_in[18];
  const float* Wg    = (const float*)d_in[19];
  const float* bg    = (const float*)d_in[20];
  const float* Wc    = (const float*)d_in[21];
  const float* bc    = (const float*)d_in[22];
  const float* Wo1   = (const float*)d_in[23];
  const float* bo1   = (const float*)d_in[24];
  const float* Wo2   = (const float*)d_in[25];
  const float* bo2   = (const float*)d_in[26];
  float* out = (float*)d_out;

  k_zeroh<<<512,256>>>();
  k_small<<<6,256>>>(SE,Wse1,bse1,Wse2,bse2,Wte1,bte1,Wte2,bte2,TE);
  k_csr<<<32,1024>>>(Ls);
  k_embed<<<6144,256>>>(X,ZC,Wconv,bconv,Win1,bin1,Win2,bin2);

  // precompute: x Chebyshev terms + combined x-part GEMM (Gx | Cx)
  k_spmm<<<1536,512>>>(0,0,1, 1.f,  0.f);
  k_spmm<<<1536,512>>>(1,0,2, 2.f, -1.f);
  k_spmm<<<1536,512>>>(2,1,3, 2.f, -1.f);
  k_gemm<192,2><<<1536,384>>>(0,1,2,3, Wg, Wc, 0, Wg, 0);

  for (int t=0;t<12;t++){
    k_spmm<<<128,512>>>(4,4,5, 1.f,  0.f);
    k_spmm<<<128,512>>>(5,4,6, 2.f, -1.f);
    k_spmm<<<128,512>>>(6,5,7, 2.f, -1.f);
    k_gemm<128,0><<<128,256>>>(4,5,6,7, Wg, Wg, 64, bg, t);
    k_spmm<<<128,512>>>(8,8,5, 1.f,  0.f);
    k_spmm<<<128,512>>>(5,8,6, 2.f, -1.f);
    k_spmm<<<128,512>>>(6,5,7, 2.f, -1.f);
    k_gemm<64,1><<<128,128>>>(8,5,6,7, Wc, Wc, 64, bc, t);
  }
  k_out<<<2048,256>>>(Wo1,bo1,Wo2,bo2,out);
}